// round 4
// baseline (speedup 1.0000x reference)
#include <cuda_runtime.h>
#include <cuda_bf16.h>
#include <cstdint>
#include <math.h>

// Problem constants (fixed by the dataset)
#define Bc 4
#define Tc 2048
#define Dc 1024
#define Hc 16
#define HDc 64
#define BT (Bc*Tc)        // 8192
#define QKV_N (3*Dc)      // 3072

// ---------------------------------------------------------------------------
// Global scratch (no cudaMalloc allowed)
// ---------------------------------------------------------------------------
__device__ float g_qkv[BT * QKV_N];        // (B*T, 3*D) fp32
__device__ float g_attn[BT * Dc];          // (B*T, D) fp32 attention out
__device__ __nv_bfloat16 g_xh[BT * Dc];    // x hi/lo bf16 (A of qkv proj)
__device__ __nv_bfloat16 g_xl[BT * Dc];
__device__ __nv_bfloat16 g_wqkv_h[QKV_N * Dc];  // Wqkv^T hi/lo, [3072,1024] K-contig
__device__ __nv_bfloat16 g_wqkv_l[QKV_N * Dc];
__device__ __nv_bfloat16 g_wout_h[Dc * Dc];     // Wout^T hi/lo, [1024,1024]
__device__ __nv_bfloat16 g_wout_l[Dc * Dc];
__device__ __nv_bfloat16 g_ah[BT * Dc];    // attn out hi/lo bf16 (A of out proj)
__device__ __nv_bfloat16 g_al[BT * Dc];

// ---------------------------------------------------------------------------
// PTX helpers (base compute_103: mma.sync + ldmatrix + cp.async)
// ---------------------------------------------------------------------------
__device__ __forceinline__ uint32_t smem_to_u32(const void* p) {
    uint32_t a;
    asm("{ .reg .u64 t; cvta.to.shared.u64 t, %1; cvt.u32.u64 %0, t; }" : "=r"(a) : "l"(p));
    return a;
}

#define CP_ASYNC_16(dst, src) \
    asm volatile("cp.async.cg.shared.global [%0], [%1], 16;" :: "r"(dst), "l"(src))
#define CP_ASYNC_COMMIT() \
    asm volatile("cp.async.commit_group;" ::: "memory")
#define CP_ASYNC_WAIT(n) \
    asm volatile("cp.async.wait_group %0;" :: "n"(n) : "memory")

#define LDSM_X4(r0, r1, r2, r3, addr) \
    asm volatile("ldmatrix.sync.aligned.m8n8.x4.shared.b16 {%0,%1,%2,%3}, [%4];" \
        : "=r"(r0), "=r"(r1), "=r"(r2), "=r"(r3) : "r"(addr))

#define MMA_BF16(d, a, b) \
    asm volatile("mma.sync.aligned.m16n8k16.row.col.f32.bf16.bf16.f32 " \
        "{%0,%1,%2,%3}, {%4,%5,%6,%7}, {%8,%9}, {%0,%1,%2,%3};" \
        : "+f"((d)[0]), "+f"((d)[1]), "+f"((d)[2]), "+f"((d)[3]) \
        : "r"((a)[0]), "r"((a)[1]), "r"((a)[2]), "r"((a)[3]), \
          "r"((b)[0]), "r"((b)[1]))

// ---------------------------------------------------------------------------
// bf16-split GEMM via mma.sync: C[M,N] = (Ah+Al)[M,K] @ (Bh+Bl)[N,K]^T, fp32.
// Tile 128x128, BK=32, 256 threads (8 warps: 2 along M x 4 along N).
// smem rows padded to 80B so ldmatrix phases are conflict-free.
// ---------------------------------------------------------------------------
#define BKc 32
#define ROWB 80                        // 32 bf16 (64B) + 16B pad
#define TILE_SB (128 * ROWB)           // 10240 B per tile
#define STAGE_SB (4 * TILE_SB)         // Ah, Al, Bh, Bl = 40960 B
#define MMA_GEMM_SMEM (2 * STAGE_SB)   // 81920 B double-buffered

__global__ __launch_bounds__(256, 1) void gemm_mma_kernel(
    const __nv_bfloat16* __restrict__ Ah, const __nv_bfloat16* __restrict__ Al,
    const __nv_bfloat16* __restrict__ Bh, const __nv_bfloat16* __restrict__ Bl,
    float* __restrict__ C, int N, int K)
{
    extern __shared__ __align__(128) char smem[];
    const uint32_t sb = smem_to_u32(smem);
    const int tid  = threadIdx.x;
    const int lane = tid & 31;
    const int wid  = tid >> 5;
    const int wm   = wid & 1;          // 0..1  (64 rows each)
    const int wn   = wid >> 1;         // 0..3  (32 cols each)
    const int m0 = blockIdx.y * 128;
    const int n0 = blockIdx.x * 128;
    const int nchunk = K / BKc;

    float acc[4][4][4];
    #pragma unroll
    for (int i = 0; i < 4; i++)
        #pragma unroll
        for (int j = 0; j < 4; j++)
            #pragma unroll
            for (int r = 0; r < 4; r++) acc[i][j][r] = 0.f;

    const __nv_bfloat16* srcs[4] = {Ah, Al, Bh, Bl};

    auto load_chunk = [&](int c, int buf) {
        #pragma unroll
        for (int t = 0; t < 4; t++) {
            const __nv_bfloat16* src = srcs[t];
            const int rbase = (t < 2) ? m0 : n0;
            #pragma unroll
            for (int i = 0; i < 2; i++) {
                int idx = tid + i * 256;          // 0..511
                int r = idx >> 2;                 // row 0..127
                int q = idx & 3;                  // 16B quarter
                uint32_t dst = sb + buf * STAGE_SB + t * TILE_SB + r * ROWB + q * 16;
                const void* g = src + (size_t)(rbase + r) * K + c * BKc + q * 8;
                CP_ASYNC_16(dst, g);
            }
        }
        CP_ASYNC_COMMIT();
    };

    load_chunk(0, 0);

    for (int c = 0; c < nchunk; c++) {
        const int buf = c & 1;
        if (c + 1 < nchunk) {
            load_chunk(c + 1, buf ^ 1);
            CP_ASYNC_WAIT(1);
        } else {
            CP_ASYNC_WAIT(0);
        }
        __syncthreads();

        const uint32_t a_base = sb + buf * STAGE_SB;
        const uint32_t b_base = a_base + 2 * TILE_SB;

        #pragma unroll
        for (int ks = 0; ks < 2; ks++) {
            // A fragments (hi and lo): 4 m-frags of m16k16
            uint32_t ah[4][4], al[4][4];
            #pragma unroll
            for (int mf = 0; mf < 4; mf++) {
                int row = wm * 64 + mf * 16 + (lane & 15);
                uint32_t col = ks * 32 + ((lane >> 4) * 16);
                uint32_t addr = a_base + row * ROWB + col;
                LDSM_X4(ah[mf][0], ah[mf][1], ah[mf][2], ah[mf][3], addr);
                LDSM_X4(al[mf][0], al[mf][1], al[mf][2], al[mf][3], addr + TILE_SB);
            }
            // B fragments (hi and lo): 4 n-frags of n8k16, loaded in pairs
            uint32_t bh[4][2], bl[4][2];
            #pragma unroll
            for (int p = 0; p < 2; p++) {
                int row = wn * 32 + p * 16 + ((lane >> 4) << 3) + (lane & 7);
                uint32_t col = ks * 32 + (((lane >> 3) & 1) * 16);
                uint32_t addr = b_base + row * ROWB + col;
                LDSM_X4(bh[2*p][0], bh[2*p][1], bh[2*p+1][0], bh[2*p+1][1], addr);
                LDSM_X4(bl[2*p][0], bl[2*p][1], bl[2*p+1][0], bl[2*p+1][1], addr + TILE_SB);
            }
            // 3-way split product: AhBh + AhBl + AlBh
            #pragma unroll
            for (int mf = 0; mf < 4; mf++)
                #pragma unroll
                for (int nf = 0; nf < 4; nf++) {
                    MMA_BF16(acc[mf][nf], ah[mf], bh[nf]);
                    MMA_BF16(acc[mf][nf], ah[mf], bl[nf]);
                    MMA_BF16(acc[mf][nf], al[mf], bh[nf]);
                }
        }
        __syncthreads();
    }

    // Epilogue: fragment layout -> fp32 global
    #pragma unroll
    for (int mf = 0; mf < 4; mf++) {
        #pragma unroll
        for (int nf = 0; nf < 4; nf++) {
            int row = m0 + wm * 64 + mf * 16 + (lane >> 2);
            int col = n0 + wn * 32 + nf * 8 + (lane & 3) * 2;
            *(float2*)&C[(size_t)row * N + col] =
                make_float2(acc[mf][nf][0], acc[mf][nf][1]);
            *(float2*)&C[(size_t)(row + 8) * N + col] =
                make_float2(acc[mf][nf][2], acc[mf][nf][3]);
        }
    }
}

// ---------------------------------------------------------------------------
// fp32 -> bf16 hi/lo split (vectorized x4)
// ---------------------------------------------------------------------------
__global__ __launch_bounds__(256) void split_kernel(
    const float4* __restrict__ in, __nv_bfloat162* __restrict__ hi,
    __nv_bfloat162* __restrict__ lo, int n4)
{
    int i = blockIdx.x * blockDim.x + threadIdx.x;
    if (i >= n4) return;
    float4 v = in[i];
    __nv_bfloat16 h0 = __float2bfloat16(v.x);
    __nv_bfloat16 h1 = __float2bfloat16(v.y);
    __nv_bfloat16 h2 = __float2bfloat16(v.z);
    __nv_bfloat16 h3 = __float2bfloat16(v.w);
    hi[2*i]   = __halves2bfloat162(h0, h1);
    hi[2*i+1] = __halves2bfloat162(h2, h3);
    lo[2*i]   = __halves2bfloat162(__float2bfloat16(v.x - __bfloat162float(h0)),
                                   __float2bfloat16(v.y - __bfloat162float(h1)));
    lo[2*i+1] = __halves2bfloat162(__float2bfloat16(v.z - __bfloat162float(h2)),
                                   __float2bfloat16(v.w - __bfloat162float(h3)));
}

// ---------------------------------------------------------------------------
// W [K,N] fp32 -> W^T [N,K] bf16 hi/lo (32x32 smem tiles)
// ---------------------------------------------------------------------------
__global__ __launch_bounds__(256) void transpose_split_kernel(
    const float* __restrict__ in, __nv_bfloat16* __restrict__ hiT,
    __nv_bfloat16* __restrict__ loT, int K, int N)
{
    __shared__ float t[32][33];
    const int tx = threadIdx.x;       // 0..31
    const int ty = threadIdx.y;       // 0..7
    const int n0 = blockIdx.x * 32;
    const int k0 = blockIdx.y * 32;
    #pragma unroll
    for (int i = 0; i < 4; i++) {
        int row = ty + i * 8;
        t[row][tx] = in[(size_t)(k0 + row) * N + n0 + tx];
    }
    __syncthreads();
    #pragma unroll
    for (int i = 0; i < 4; i++) {
        int row = ty + i * 8;
        float v = t[tx][row];                       // in[k0+tx][n0+row]
        __nv_bfloat16 h = __float2bfloat16(v);
        size_t o = (size_t)(n0 + row) * K + k0 + tx;
        hiT[o] = h;
        loT[o] = __float2bfloat16(v - __bfloat162float(h));
    }
}

// ---------------------------------------------------------------------------
// Flash-style attention (unchanged from passing round)
// ---------------------------------------------------------------------------
#define ATT_SMEM_BYTES ((4096 + 4160 + 4160) * 4)

__global__ __launch_bounds__(256) void attn_kernel(
    const float* __restrict__ qkv,   // (B*T, 3072)
    const int*   __restrict__ pos,   // (B*T)
    float*       __restrict__ out)   // (B*T, 1024) as (B,T,H,HD)
{
    extern __shared__ float sm[];
    float* Qs = sm;                 // [64][64]
    float* Ks = sm + 4096;          // [64][65]  (later reused as P)
    float* Vs = sm + 4096 + 4160;   // [64][65]

    const int tid = threadIdx.x;
    const int tx  = tid & 15;
    const int ty  = tid >> 4;

    const int q0 = blockIdx.x * 64;
    const int h  = blockIdx.y;
    const int b  = blockIdx.z;
    const int bt0 = b * Tc + q0;

    const float scale = 0.125f;

    for (int i = tid; i < 64 * 64; i += 256) {
        int r = i >> 6, c = i & 63;
        Qs[r * 64 + c] = qkv[(size_t)(bt0 + r) * QKV_N + h * HDc + c] * scale;
    }

    int pq[4];
    #pragma unroll
    for (int r = 0; r < 4; r++) pq[r] = pos[bt0 + ty * 4 + r];
    const int pq_block_max = pos[bt0 + 63];

    float m[4], l[4], O[4][4];
    #pragma unroll
    for (int r = 0; r < 4; r++) { m[r] = -1e30f; l[r] = 0.f; }
    #pragma unroll
    for (int r = 0; r < 4; r++)
        #pragma unroll
        for (int c = 0; c < 4; c++) O[r][c] = 0.f;

    __syncthreads();

    for (int k0 = 0; k0 < Tc; k0 += 64) {
        if (pos[b * Tc + k0] > pq_block_max) break;

        for (int i = tid; i < 64 * 64; i += 256) {
            int j = i >> 6, c = i & 63;
            size_t base = (size_t)(b * Tc + k0 + j) * QKV_N + h * HDc + c;
            Ks[j * 65 + c] = qkv[base + 1024];
            Vs[j * 65 + c] = qkv[base + 2048];
        }
        __syncthreads();

        int pk[4];
        #pragma unroll
        for (int c = 0; c < 4; c++) pk[c] = pos[b * Tc + k0 + tx * 4 + c];

        float s[4][4];
        #pragma unroll
        for (int r = 0; r < 4; r++)
            #pragma unroll
            for (int c = 0; c < 4; c++) s[r][c] = 0.f;

        #pragma unroll 4
        for (int k = 0; k < 64; k++) {
            float ra[4], rb[4];
            #pragma unroll
            for (int r = 0; r < 4; r++) ra[r] = Qs[(ty * 4 + r) * 64 + k];
            #pragma unroll
            for (int c = 0; c < 4; c++) rb[c] = Ks[(tx * 4 + c) * 65 + k];
            #pragma unroll
            for (int r = 0; r < 4; r++)
                #pragma unroll
                for (int c = 0; c < 4; c++)
                    s[r][c] += ra[r] * rb[c];
        }

        float alpha[4];
        #pragma unroll
        for (int r = 0; r < 4; r++) {
            float rowmax = -1e30f;
            #pragma unroll
            for (int c = 0; c < 4; c++) {
                if (pk[c] > pq[r]) s[r][c] = -1e30f;
                rowmax = fmaxf(rowmax, s[r][c]);
            }
            #pragma unroll
            for (int off = 8; off >= 1; off >>= 1)
                rowmax = fmaxf(rowmax, __shfl_xor_sync(0xffffffffu, rowmax, off));

            float mnew = fmaxf(m[r], rowmax);
            alpha[r] = __expf(m[r] - mnew);

            float psum = 0.f;
            #pragma unroll
            for (int c = 0; c < 4; c++) {
                float p = __expf(s[r][c] - mnew);
                s[r][c] = p;
                psum += p;
            }
            #pragma unroll
            for (int off = 8; off >= 1; off >>= 1)
                psum += __shfl_xor_sync(0xffffffffu, psum, off);

            l[r] = l[r] * alpha[r] + psum;
            m[r] = mnew;
        }

        __syncthreads();
        #pragma unroll
        for (int r = 0; r < 4; r++)
            #pragma unroll
            for (int c = 0; c < 4; c++)
                Ks[(ty * 4 + r) * 65 + tx * 4 + c] = s[r][c];
        __syncthreads();

        #pragma unroll
        for (int r = 0; r < 4; r++)
            #pragma unroll
            for (int c = 0; c < 4; c++)
                O[r][c] *= alpha[r];

        #pragma unroll 4
        for (int j = 0; j < 64; j++) {
            float pr[4], vv[4];
            #pragma unroll
            for (int r = 0; r < 4; r++) pr[r] = Ks[(ty * 4 + r) * 65 + j];
            #pragma unroll
            for (int c = 0; c < 4; c++) vv[c] = Vs[j * 65 + tx * 4 + c];
            #pragma unroll
            for (int r = 0; r < 4; r++)
                #pragma unroll
                for (int c = 0; c < 4; c++)
                    O[r][c] += pr[r] * vv[c];
        }
        __syncthreads();
    }

    #pragma unroll
    for (int r = 0; r < 4; r++) {
        float inv_l = 1.0f / l[r];
        int row = ty * 4 + r;
        #pragma unroll
        for (int c = 0; c < 4; c++) {
            out[(size_t)(bt0 + row) * Dc + h * HDc + tx * 4 + c] = O[r][c] * inv_l;
        }
    }
}

// ---------------------------------------------------------------------------
extern "C" void kernel_launch(void* const* d_in, const int* in_sizes, int n_in,
                              void* d_out, int out_size)
{
    const float* x    = (const float*)d_in[0];   // (B,T,D)
    const int*   pos  = (const int*)  d_in[1];   // (B,T)
    const float* Wqkv = (const float*)d_in[2];   // (D, 3D)
    const float* Wout = (const float*)d_in[3];   // (D, D)
    float* out = (float*)d_out;                  // (B,T,D)

    float *qkv_ptr = nullptr, *attn_ptr = nullptr;
    __nv_bfloat16 *xh, *xl, *wqh, *wql, *woh, *wol, *ah, *al;
    cudaGetSymbolAddress((void**)&qkv_ptr,  g_qkv);
    cudaGetSymbolAddress((void**)&attn_ptr, g_attn);
    cudaGetSymbolAddress((void**)&xh,  g_xh);
    cudaGetSymbolAddress((void**)&xl,  g_xl);
    cudaGetSymbolAddress((void**)&wqh, g_wqkv_h);
    cudaGetSymbolAddress((void**)&wql, g_wqkv_l);
    cudaGetSymbolAddress((void**)&woh, g_wout_h);
    cudaGetSymbolAddress((void**)&wol, g_wout_l);
    cudaGetSymbolAddress((void**)&ah,  g_ah);
    cudaGetSymbolAddress((void**)&al,  g_al);

    static bool attr_set = false;
    if (!attr_set) {
        cudaFuncSetAttribute(gemm_mma_kernel,
                             cudaFuncAttributeMaxDynamicSharedMemorySize, MMA_GEMM_SMEM);
        cudaFuncSetAttribute(attn_kernel,
                             cudaFuncAttributeMaxDynamicSharedMemorySize, ATT_SMEM_BYTES);
        attr_set = true;
    }

    // 0a) Split x -> bf16 hi/lo
    {
        int n4 = BT * Dc / 4;
        split_kernel<<<(n4 + 255) / 256, 256>>>(
            (const float4*)x, (__nv_bfloat162*)xh, (__nv_bfloat162*)xl, n4);
    }
    // 0b) Transpose+split weights
    {
        dim3 grid(QKV_N / 32, Dc / 32);
        transpose_split_kernel<<<grid, dim3(32, 8)>>>(Wqkv, wqh, wql, Dc, QKV_N);
    }
    {
        dim3 grid(Dc / 32, Dc / 32);
        transpose_split_kernel<<<grid, dim3(32, 8)>>>(Wout, woh, wol, Dc, Dc);
    }

    // 1) QKV projection on HMMA: (8192,1024) @ (1024,3072)
    {
        dim3 grid(QKV_N / 128, BT / 128);
        gemm_mma_kernel<<<grid, 256, MMA_GEMM_SMEM>>>(
            xh, xl, wqh, wql, qkv_ptr, QKV_N, Dc);
    }

    // 2) Attention (fp32 flash)
    {
        dim3 grid(Tc / 64, Hc, Bc);
        attn_kernel<<<grid, 256, ATT_SMEM_BYTES>>>(qkv_ptr, pos, attn_ptr);
    }

    // 3) Split attention output, then out projection on HMMA
    {
        int n4 = BT * Dc / 4;
        split_kernel<<<(n4 + 255) / 256, 256>>>(
            (const float4*)attn_ptr, (__nv_bfloat162*)ah, (__nv_bfloat162*)al, n4);
    }
    {
        dim3 grid(Dc / 128, BT / 128);
        gemm_mma_kernel<<<grid, 256, MMA_GEMM_SMEM>>>(
            ah, al, woh, wol, out, Dc, Dc);
    }
}

// round 5
// speedup vs baseline: 2.3179x; 2.3179x over previous
#include <cuda_runtime.h>
#include <cuda_bf16.h>
#include <cstdint>
#include <math.h>

// Problem constants (fixed by the dataset)
#define Bc 4
#define Tc 2048
#define Dc 1024
#define Hc 16
#define HDc 64
#define BT (Bc*Tc)        // 8192
#define QKV_N (3*Dc)      // 3072

// ---------------------------------------------------------------------------
// Global scratch (no cudaMalloc allowed)
// ---------------------------------------------------------------------------
__device__ float g_qkv[BT * QKV_N];        // (B*T, 3*D) fp32
__device__ __nv_bfloat16 g_xh[BT * Dc];    // x hi/lo bf16 (A of qkv proj)
__device__ __nv_bfloat16 g_xl[BT * Dc];
__device__ __nv_bfloat16 g_wqkv_h[QKV_N * Dc];  // Wqkv^T hi/lo, [3072,1024] K-contig
__device__ __nv_bfloat16 g_wqkv_l[QKV_N * Dc];
__device__ __nv_bfloat16 g_wout_h[Dc * Dc];     // Wout^T hi/lo, [1024,1024]
__device__ __nv_bfloat16 g_wout_l[Dc * Dc];
__device__ __nv_bfloat16 g_ah[BT * Dc];    // attn out hi/lo bf16 (A of out proj)
__device__ __nv_bfloat16 g_al[BT * Dc];

// ---------------------------------------------------------------------------
// PTX helpers (base compute_103: mma.sync + ldmatrix + cp.async)
// ---------------------------------------------------------------------------
__device__ __forceinline__ uint32_t smem_to_u32(const void* p) {
    uint32_t a;
    asm("{ .reg .u64 t; cvta.to.shared.u64 t, %1; cvt.u32.u64 %0, t; }" : "=r"(a) : "l"(p));
    return a;
}

#define CP_ASYNC_16(dst, src) \
    asm volatile("cp.async.cg.shared.global [%0], [%1], 16;" :: "r"(dst), "l"(src))
#define CP_ASYNC_COMMIT() \
    asm volatile("cp.async.commit_group;" ::: "memory")
#define CP_ASYNC_WAIT(n) \
    asm volatile("cp.async.wait_group %0;" :: "n"(n) : "memory")

#define LDSM_X4(r0, r1, r2, r3, addr) \
    asm volatile("ldmatrix.sync.aligned.m8n8.x4.shared.b16 {%0,%1,%2,%3}, [%4];" \
        : "=r"(r0), "=r"(r1), "=r"(r2), "=r"(r3) : "r"(addr))

#define MMA_BF16(d, a, b) \
    asm volatile("mma.sync.aligned.m16n8k16.row.col.f32.bf16.bf16.f32 " \
        "{%0,%1,%2,%3}, {%4,%5,%6,%7}, {%8,%9}, {%0,%1,%2,%3};" \
        : "+f"((d)[0]), "+f"((d)[1]), "+f"((d)[2]), "+f"((d)[3]) \
        : "r"((a)[0]), "r"((a)[1]), "r"((a)[2]), "r"((a)[3]), \
          "r"((b)[0]), "r"((b)[1]))

#define MMA_AB(d, a, b0v, b1v) \
    asm volatile("mma.sync.aligned.m16n8k16.row.col.f32.bf16.bf16.f32 " \
        "{%0,%1,%2,%3}, {%4,%5,%6,%7}, {%8,%9}, {%0,%1,%2,%3};" \
        : "+f"((d)[0]), "+f"((d)[1]), "+f"((d)[2]), "+f"((d)[3]) \
        : "r"((a)[0]), "r"((a)[1]), "r"((a)[2]), "r"((a)[3]), \
          "r"(b0v), "r"(b1v))

// Split a pair of fp32 into packed bf16x2 hi and lo (residual) words.
__device__ __forceinline__ void split2(float a, float b, uint32_t& hi, uint32_t& lo) {
    __nv_bfloat16 ha = __float2bfloat16(a), hb = __float2bfloat16(b);
    __nv_bfloat162 hh = __halves2bfloat162(ha, hb);
    __nv_bfloat162 ll = __halves2bfloat162(
        __float2bfloat16(a - __bfloat162float(ha)),
        __float2bfloat16(b - __bfloat162float(hb)));
    hi = *(uint32_t*)&hh;
    lo = *(uint32_t*)&ll;
}

// ---------------------------------------------------------------------------
// bf16-split GEMM via mma.sync: C[M,N] = (Ah+Al)[M,K] @ (Bh+Bl)[N,K]^T, fp32.
// (unchanged structure from the passing round; split loops reordered for ILP)
// ---------------------------------------------------------------------------
#define BKc 32
#define ROWB 80
#define TILE_SB (128 * ROWB)
#define STAGE_SB (4 * TILE_SB)
#define MMA_GEMM_SMEM (2 * STAGE_SB)

__global__ __launch_bounds__(256, 1) void gemm_mma_kernel(
    const __nv_bfloat16* __restrict__ Ah, const __nv_bfloat16* __restrict__ Al,
    const __nv_bfloat16* __restrict__ Bh, const __nv_bfloat16* __restrict__ Bl,
    float* __restrict__ C, int N, int K)
{
    extern __shared__ __align__(128) char smem[];
    const uint32_t sb = smem_to_u32(smem);
    const int tid  = threadIdx.x;
    const int lane = tid & 31;
    const int wid  = tid >> 5;
    const int wm   = wid & 1;
    const int wn   = wid >> 1;
    const int m0 = blockIdx.y * 128;
    const int n0 = blockIdx.x * 128;
    const int nchunk = K / BKc;

    float acc[4][4][4];
    #pragma unroll
    for (int i = 0; i < 4; i++)
        #pragma unroll
        for (int j = 0; j < 4; j++)
            #pragma unroll
            for (int r = 0; r < 4; r++) acc[i][j][r] = 0.f;

    const __nv_bfloat16* srcs[4] = {Ah, Al, Bh, Bl};

    auto load_chunk = [&](int c, int buf) {
        #pragma unroll
        for (int t = 0; t < 4; t++) {
            const __nv_bfloat16* src = srcs[t];
            const int rbase = (t < 2) ? m0 : n0;
            #pragma unroll
            for (int i = 0; i < 2; i++) {
                int idx = tid + i * 256;
                int r = idx >> 2;
                int q = idx & 3;
                uint32_t dst = sb + buf * STAGE_SB + t * TILE_SB + r * ROWB + q * 16;
                const void* g = src + (size_t)(rbase + r) * K + c * BKc + q * 8;
                CP_ASYNC_16(dst, g);
            }
        }
        CP_ASYNC_COMMIT();
    };

    load_chunk(0, 0);

    for (int c = 0; c < nchunk; c++) {
        const int buf = c & 1;
        if (c + 1 < nchunk) {
            load_chunk(c + 1, buf ^ 1);
            CP_ASYNC_WAIT(1);
        } else {
            CP_ASYNC_WAIT(0);
        }
        __syncthreads();

        const uint32_t a_base = sb + buf * STAGE_SB;
        const uint32_t b_base = a_base + 2 * TILE_SB;

        #pragma unroll
        for (int ks = 0; ks < 2; ks++) {
            uint32_t ah[4][4], al[4][4];
            #pragma unroll
            for (int mf = 0; mf < 4; mf++) {
                int row = wm * 64 + mf * 16 + (lane & 15);
                uint32_t col = ks * 32 + ((lane >> 4) * 16);
                uint32_t addr = a_base + row * ROWB + col;
                LDSM_X4(ah[mf][0], ah[mf][1], ah[mf][2], ah[mf][3], addr);
                LDSM_X4(al[mf][0], al[mf][1], al[mf][2], al[mf][3], addr + TILE_SB);
            }
            uint32_t bh[4][2], bl[4][2];
            #pragma unroll
            for (int p = 0; p < 2; p++) {
                int row = wn * 32 + p * 16 + ((lane >> 4) << 3) + (lane & 7);
                uint32_t col = ks * 32 + (((lane >> 3) & 1) * 16);
                uint32_t addr = b_base + row * ROWB + col;
                LDSM_X4(bh[2*p][0], bh[2*p][1], bh[2*p+1][0], bh[2*p+1][1], addr);
                LDSM_X4(bl[2*p][0], bl[2*p][1], bl[2*p+1][0], bl[2*p+1][1], addr + TILE_SB);
            }
            // split products grouped by term: 16 independent MMAs between
            // dependent accumulations on the same acc tile
            #pragma unroll
            for (int mf = 0; mf < 4; mf++)
                #pragma unroll
                for (int nf = 0; nf < 4; nf++)
                    MMA_BF16(acc[mf][nf], ah[mf], bh[nf]);
            #pragma unroll
            for (int mf = 0; mf < 4; mf++)
                #pragma unroll
                for (int nf = 0; nf < 4; nf++)
                    MMA_BF16(acc[mf][nf], ah[mf], bl[nf]);
            #pragma unroll
            for (int mf = 0; mf < 4; mf++)
                #pragma unroll
                for (int nf = 0; nf < 4; nf++)
                    MMA_BF16(acc[mf][nf], al[mf], bh[nf]);
        }
        __syncthreads();
    }

    #pragma unroll
    for (int mf = 0; mf < 4; mf++) {
        #pragma unroll
        for (int nf = 0; nf < 4; nf++) {
            int row = m0 + wm * 64 + mf * 16 + (lane >> 2);
            int col = n0 + wn * 32 + nf * 8 + (lane & 3) * 2;
            *(float2*)&C[(size_t)row * N + col] =
                make_float2(acc[mf][nf][0], acc[mf][nf][1]);
            *(float2*)&C[(size_t)(row + 8) * N + col] =
                make_float2(acc[mf][nf][2], acc[mf][nf][3]);
        }
    }
}

// ---------------------------------------------------------------------------
// HMMA flash attention with position-derived causal mask + fused output split.
// Grid (T/128, H, B), 256 threads (8 warps x 16 rows each).
// smem byte layout (row stride 144B = 72 bf16, odd multiple of 16B =>
// conflict-free ldmatrix):
//   Qh 0..18432, Ql ..36864, Kh ..46080, Kl ..55296,
//   Vh(T) ..64512, Vl(T) ..73728, pos ..73984
// ---------------------------------------------------------------------------
#define AT_ROW 72
#define QHB 0
#define QLB 18432
#define KHB 36864
#define KLB 46080
#define VHB 55296
#define VLB 64512
#define POSB 73728
#define ATTN_SMEM (POSB + 64*4)

__global__ __launch_bounds__(256) void attn_mma_kernel(
    const float* __restrict__ qkv,        // (B*T, 3072) fp32
    const int*   __restrict__ pos,        // (B*T)
    __nv_bfloat16* __restrict__ outh,     // (B*T, 1024) bf16 hi
    __nv_bfloat16* __restrict__ outl)     // (B*T, 1024) bf16 lo
{
    extern __shared__ __align__(128) char smem[];
    const uint32_t sb = smem_to_u32(smem);
    int* spos = (int*)(smem + POSB);

    const int tid  = threadIdx.x;
    const int lane = tid & 31;
    const int wid  = tid >> 5;

    const int q0  = blockIdx.x * 128;
    const int h   = blockIdx.y;
    const int b   = blockIdx.z;
    const int bt0 = b * Tc + q0;
    const int bT  = b * Tc;

    // Load + scale + split Q into smem (scale 0.125 is a power of 2: exact)
    for (int i = tid; i < 128 * 64; i += 256) {
        int r = i >> 6, c = i & 63;
        float v = qkv[(size_t)(bt0 + r) * QKV_N + h * HDc + c] * 0.125f;
        __nv_bfloat16 hh = __float2bfloat16(v);
        ((__nv_bfloat16*)(smem + QHB))[r * AT_ROW + c] = hh;
        ((__nv_bfloat16*)(smem + QLB))[r * AT_ROW + c] =
            __float2bfloat16(v - __bfloat162float(hh));
    }
    const int pq0 = pos[bt0 + wid * 16 + (lane >> 2)];
    const int pq1 = pos[bt0 + wid * 16 + (lane >> 2) + 8];
    const int pqmax = pos[bt0 + 127];
    __syncthreads();

    // Q fragments in registers for the whole kernel (16 rows per warp, k=64)
    uint32_t qh[4][4], ql[4][4];
    #pragma unroll
    for (int ks = 0; ks < 4; ks++) {
        uint32_t addr = sb + QHB + (wid * 16 + (lane & 15)) * 144
                      + ks * 32 + (lane >> 4) * 16;
        LDSM_X4(qh[ks][0], qh[ks][1], qh[ks][2], qh[ks][3], addr);
        LDSM_X4(ql[ks][0], ql[ks][1], ql[ks][2], ql[ks][3], addr + (QLB - QHB));
    }

    float m0 = -1e30f, m1 = -1e30f, l0 = 0.f, l1 = 0.f;
    float oacc[8][4];
    #pragma unroll
    for (int nf = 0; nf < 8; nf++)
        #pragma unroll
        for (int r = 0; r < 4; r++) oacc[nf][r] = 0.f;

    for (int k0 = 0; k0 < Tc; k0 += 64) {
        if (pos[bT + k0] > pqmax) break;   // sorted positions: rest fully masked

        // Convert K (row-major) and V (transposed) tiles to bf16 hi/lo
        for (int i = tid; i < 64 * 64; i += 256) {
            int j = i >> 6, c = i & 63;
            size_t base = (size_t)(bT + k0 + j) * QKV_N + h * HDc + c;
            float kv = qkv[base + Dc];
            float vv = qkv[base + 2 * Dc];
            __nv_bfloat16 kh = __float2bfloat16(kv);
            ((__nv_bfloat16*)(smem + KHB))[j * AT_ROW + c] = kh;
            ((__nv_bfloat16*)(smem + KLB))[j * AT_ROW + c] =
                __float2bfloat16(kv - __bfloat162float(kh));
            __nv_bfloat16 vh = __float2bfloat16(vv);
            ((__nv_bfloat16*)(smem + VHB))[c * AT_ROW + j] = vh;   // transpose
            ((__nv_bfloat16*)(smem + VLB))[c * AT_ROW + j] =
                __float2bfloat16(vv - __bfloat162float(vh));
        }
        if (tid < 64) spos[tid] = pos[bT + k0 + tid];
        __syncthreads();

        // S = Q K^T (hi/lo split, fp32 accum): 8 n-frags x 4 k-steps
        float sacc[8][4];
        #pragma unroll
        for (int nf = 0; nf < 8; nf++)
            #pragma unroll
            for (int r = 0; r < 4; r++) sacc[nf][r] = 0.f;

        #pragma unroll
        for (int ks = 0; ks < 4; ks++) {
            #pragma unroll
            for (int p = 0; p < 4; p++) {
                uint32_t row = p * 16 + ((lane >> 4) << 3) + (lane & 7);
                uint32_t addr = sb + KHB + row * 144
                              + ks * 32 + (((lane >> 3) & 1) * 16);
                uint32_t h0, h1, h2, h3, lo0, lo1, lo2, lo3;
                LDSM_X4(h0, h1, h2, h3, addr);
                LDSM_X4(lo0, lo1, lo2, lo3, addr + (KLB - KHB));
                MMA_AB(sacc[2*p],   qh[ks], h0, h1);
                MMA_AB(sacc[2*p],   qh[ks], lo0, lo1);
                MMA_AB(sacc[2*p],   ql[ks], h0, h1);
                MMA_AB(sacc[2*p+1], qh[ks], h2, h3);
                MMA_AB(sacc[2*p+1], qh[ks], lo2, lo3);
                MMA_AB(sacc[2*p+1], ql[ks], h2, h3);
            }
        }

        // Mask + online softmax (rows owned by 4-lane groups: xor 1,2)
        float mx0 = -1e30f, mx1 = -1e30f;
        #pragma unroll
        for (int nf = 0; nf < 8; nf++) {
            int jc = nf * 8 + (lane & 3) * 2;
            int p0 = spos[jc], p1 = spos[jc + 1];
            if (p0 > pq0) sacc[nf][0] = -1e30f;
            if (p1 > pq0) sacc[nf][1] = -1e30f;
            if (p0 > pq1) sacc[nf][2] = -1e30f;
            if (p1 > pq1) sacc[nf][3] = -1e30f;
            mx0 = fmaxf(mx0, fmaxf(sacc[nf][0], sacc[nf][1]));
            mx1 = fmaxf(mx1, fmaxf(sacc[nf][2], sacc[nf][3]));
        }
        mx0 = fmaxf(mx0, __shfl_xor_sync(0xffffffffu, mx0, 1));
        mx0 = fmaxf(mx0, __shfl_xor_sync(0xffffffffu, mx0, 2));
        mx1 = fmaxf(mx1, __shfl_xor_sync(0xffffffffu, mx1, 1));
        mx1 = fmaxf(mx1, __shfl_xor_sync(0xffffffffu, mx1, 2));

        float mn0 = fmaxf(m0, mx0), mn1 = fmaxf(m1, mx1);
        float al0 = __expf(m0 - mn0), al1 = __expf(m1 - mn1);
        float ps0 = 0.f, ps1 = 0.f;
        #pragma unroll
        for (int nf = 0; nf < 8; nf++) {
            sacc[nf][0] = __expf(sacc[nf][0] - mn0); ps0 += sacc[nf][0];
            sacc[nf][1] = __expf(sacc[nf][1] - mn0); ps0 += sacc[nf][1];
            sacc[nf][2] = __expf(sacc[nf][2] - mn1); ps1 += sacc[nf][2];
            sacc[nf][3] = __expf(sacc[nf][3] - mn1); ps1 += sacc[nf][3];
        }
        ps0 += __shfl_xor_sync(0xffffffffu, ps0, 1);
        ps0 += __shfl_xor_sync(0xffffffffu, ps0, 2);
        ps1 += __shfl_xor_sync(0xffffffffu, ps1, 1);
        ps1 += __shfl_xor_sync(0xffffffffu, ps1, 2);
        l0 = l0 * al0 + ps0;  m0 = mn0;
        l1 = l1 * al1 + ps1;  m1 = mn1;
        #pragma unroll
        for (int nf = 0; nf < 8; nf++) {
            oacc[nf][0] *= al0; oacc[nf][1] *= al0;
            oacc[nf][2] *= al1; oacc[nf][3] *= al1;
        }

        // O += P V (P split hi/lo in-register; S-accum frag == PV A frag)
        #pragma unroll
        for (int ksp = 0; ksp < 4; ksp++) {
            uint32_t ph[4], pl[4];
            split2(sacc[2*ksp][0],   sacc[2*ksp][1],   ph[0], pl[0]);
            split2(sacc[2*ksp][2],   sacc[2*ksp][3],   ph[1], pl[1]);
            split2(sacc[2*ksp+1][0], sacc[2*ksp+1][1], ph[2], pl[2]);
            split2(sacc[2*ksp+1][2], sacc[2*ksp+1][3], ph[3], pl[3]);
            #pragma unroll
            for (int p = 0; p < 4; p++) {
                uint32_t row = p * 16 + ((lane >> 4) << 3) + (lane & 7);
                uint32_t addr = sb + VHB + row * 144
                              + ksp * 32 + (((lane >> 3) & 1) * 16);
                uint32_t v0, v1, v2, v3, w0, w1, w2, w3;
                LDSM_X4(v0, v1, v2, v3, addr);
                LDSM_X4(w0, w1, w2, w3, addr + (VLB - VHB));
                MMA_AB(oacc[2*p],   ph, v0, v1);
                MMA_AB(oacc[2*p],   ph, w0, w1);
                MMA_AB(oacc[2*p],   pl, v0, v1);
                MMA_AB(oacc[2*p+1], ph, v2, v3);
                MMA_AB(oacc[2*p+1], ph, w2, w3);
                MMA_AB(oacc[2*p+1], pl, v2, v3);
            }
        }
        __syncthreads();
    }

    // Epilogue: normalize and write bf16 hi/lo (fused split for out-proj)
    const float inv0 = 1.0f / l0;
    const float inv1 = 1.0f / l1;
    const int r0 = bt0 + wid * 16 + (lane >> 2);
    const int r1 = r0 + 8;
    #pragma unroll
    for (int nf = 0; nf < 8; nf++) {
        int col = h * HDc + nf * 8 + (lane & 3) * 2;
        uint32_t hi, lo;
        split2(oacc[nf][0] * inv0, oacc[nf][1] * inv0, hi, lo);
        *(uint32_t*)&outh[(size_t)r0 * Dc + col] = hi;
        *(uint32_t*)&outl[(size_t)r0 * Dc + col] = lo;
        split2(oacc[nf][2] * inv1, oacc[nf][3] * inv1, hi, lo);
        *(uint32_t*)&outh[(size_t)r1 * Dc + col] = hi;
        *(uint32_t*)&outl[(size_t)r1 * Dc + col] = lo;
    }
}

// ---------------------------------------------------------------------------
// fp32 -> bf16 hi/lo split (vectorized x4)
// ---------------------------------------------------------------------------
__global__ __launch_bounds__(256) void split_kernel(
    const float4* __restrict__ in, __nv_bfloat162* __restrict__ hi,
    __nv_bfloat162* __restrict__ lo, int n4)
{
    int i = blockIdx.x * blockDim.x + threadIdx.x;
    if (i >= n4) return;
    float4 v = in[i];
    __nv_bfloat16 h0 = __float2bfloat16(v.x);
    __nv_bfloat16 h1 = __float2bfloat16(v.y);
    __nv_bfloat16 h2 = __float2bfloat16(v.z);
    __nv_bfloat16 h3 = __float2bfloat16(v.w);
    hi[2*i]   = __halves2bfloat162(h0, h1);
    hi[2*i+1] = __halves2bfloat162(h2, h3);
    lo[2*i]   = __halves2bfloat162(__float2bfloat16(v.x - __bfloat162float(h0)),
                                   __float2bfloat16(v.y - __bfloat162float(h1)));
    lo[2*i+1] = __halves2bfloat162(__float2bfloat16(v.z - __bfloat162float(h2)),
                                   __float2bfloat16(v.w - __bfloat162float(h3)));
}

// ---------------------------------------------------------------------------
// W [K,N] fp32 -> W^T [N,K] bf16 hi/lo (32x32 smem tiles)
// ---------------------------------------------------------------------------
__global__ __launch_bounds__(256) void transpose_split_kernel(
    const float* __restrict__ in, __nv_bfloat16* __restrict__ hiT,
    __nv_bfloat16* __restrict__ loT, int K, int N)
{
    __shared__ float t[32][33];
    const int tx = threadIdx.x;
    const int ty = threadIdx.y;
    const int n0 = blockIdx.x * 32;
    const int k0 = blockIdx.y * 32;
    #pragma unroll
    for (int i = 0; i < 4; i++) {
        int row = ty + i * 8;
        t[row][tx] = in[(size_t)(k0 + row) * N + n0 + tx];
    }
    __syncthreads();
    #pragma unroll
    for (int i = 0; i < 4; i++) {
        int row = ty + i * 8;
        float v = t[tx][row];
        __nv_bfloat16 h = __float2bfloat16(v);
        size_t o = (size_t)(n0 + row) * K + k0 + tx;
        hiT[o] = h;
        loT[o] = __float2bfloat16(v - __bfloat162float(h));
    }
}

// ---------------------------------------------------------------------------
extern "C" void kernel_launch(void* const* d_in, const int* in_sizes, int n_in,
                              void* d_out, int out_size)
{
    const float* x    = (const float*)d_in[0];   // (B,T,D)
    const int*   pos  = (const int*)  d_in[1];   // (B,T)
    const float* Wqkv = (const float*)d_in[2];   // (D, 3D)
    const float* Wout = (const float*)d_in[3];   // (D, D)
    float* out = (float*)d_out;                  // (B,T,D)

    float *qkv_ptr = nullptr;
    __nv_bfloat16 *xh, *xl, *wqh, *wql, *woh, *wol, *ah, *al;
    cudaGetSymbolAddress((void**)&qkv_ptr,  g_qkv);
    cudaGetSymbolAddress((void**)&xh,  g_xh);
    cudaGetSymbolAddress((void**)&xl,  g_xl);
    cudaGetSymbolAddress((void**)&wqh, g_wqkv_h);
    cudaGetSymbolAddress((void**)&wql, g_wqkv_l);
    cudaGetSymbolAddress((void**)&woh, g_wout_h);
    cudaGetSymbolAddress((void**)&wol, g_wout_l);
    cudaGetSymbolAddress((void**)&ah,  g_ah);
    cudaGetSymbolAddress((void**)&al,  g_al);

    static bool attr_set = false;
    if (!attr_set) {
        cudaFuncSetAttribute(gemm_mma_kernel,
                             cudaFuncAttributeMaxDynamicSharedMemorySize, MMA_GEMM_SMEM);
        cudaFuncSetAttribute(attn_mma_kernel,
                             cudaFuncAttributeMaxDynamicSharedMemorySize, ATTN_SMEM);
        attr_set = true;
    }

    // 0a) Split x -> bf16 hi/lo
    {
        int n4 = BT * Dc / 4;
        split_kernel<<<(n4 + 255) / 256, 256>>>(
            (const float4*)x, (__nv_bfloat162*)xh, (__nv_bfloat162*)xl, n4);
    }
    // 0b) Transpose+split weights
    {
        dim3 grid(QKV_N / 32, Dc / 32);
        transpose_split_kernel<<<grid, dim3(32, 8)>>>(Wqkv, wqh, wql, Dc, QKV_N);
    }
    {
        dim3 grid(Dc / 32, Dc / 32);
        transpose_split_kernel<<<grid, dim3(32, 8)>>>(Wout, woh, wol, Dc, Dc);
    }

    // 1) QKV projection on HMMA: (8192,1024) @ (1024,3072)
    {
        dim3 grid(QKV_N / 128, BT / 128);
        gemm_mma_kernel<<<grid, 256, MMA_GEMM_SMEM>>>(
            xh, xl, wqh, wql, qkv_ptr, QKV_N, Dc);
    }

    // 2) Attention on HMMA (fused output hi/lo split)
    {
        dim3 grid(Tc / 128, Hc, Bc);
        attn_mma_kernel<<<grid, 256, ATTN_SMEM>>>(qkv_ptr, pos, ah, al);
    }

    // 3) Out projection on HMMA
    {
        dim3 grid(Dc / 128, BT / 128);
        gemm_mma_kernel<<<grid, 256, MMA_GEMM_SMEM>>>(
            ah, al, woh, wol, out, Dc, Dc);
    }
}

// round 9
// speedup vs baseline: 3.0894x; 1.3328x over previous
#include <cuda_runtime.h>
#include <cuda_bf16.h>
#include <cstdint>
#include <math.h>

// Problem constants (fixed by the dataset)
#define Bc 4
#define Tc 2048
#define Dc 1024
#define Hc 16
#define HDc 64
#define BT (Bc*Tc)        // 8192
#define QKV_N (3*Dc)      // 3072

// ---------------------------------------------------------------------------
// Global scratch (no cudaMalloc allowed)
// ---------------------------------------------------------------------------
__device__ float g_qkv[BT * QKV_N];        // (B*T, 3*D) fp32
__device__ __nv_bfloat16 g_xh[BT * Dc];
__device__ __nv_bfloat16 g_xl[BT * Dc];
__device__ __nv_bfloat16 g_wqkv_h[QKV_N * Dc];  // Wqkv^T hi/lo, [3072,1024]
__device__ __nv_bfloat16 g_wqkv_l[QKV_N * Dc];
__device__ __nv_bfloat16 g_wout_h[Dc * Dc];
__device__ __nv_bfloat16 g_wout_l[Dc * Dc];
__device__ __nv_bfloat16 g_ah[BT * Dc];    // attention out hi/lo (A of out proj)
__device__ __nv_bfloat16 g_al[BT * Dc];
// Pre-converted attention operands:
__device__ __nv_bfloat16 g_qh[Bc * Hc * Tc * HDc];   // [B][H][T][64] scaled
__device__ __nv_bfloat16 g_ql[Bc * Hc * Tc * HDc];
__device__ __nv_bfloat16 g_kh[Bc * Hc * Tc * HDc];   // [B][H][T][64]
__device__ __nv_bfloat16 g_kl[Bc * Hc * Tc * HDc];
__device__ __nv_bfloat16 g_vh[Bc * Hc * HDc * Tc];   // [B][H][64][T] transposed
__device__ __nv_bfloat16 g_vl[Bc * Hc * HDc * Tc];

// ---------------------------------------------------------------------------
// PTX helpers (base compute_103: mma.sync + ldmatrix + cp.async)
// ---------------------------------------------------------------------------
__device__ __forceinline__ uint32_t smem_to_u32(const void* p) {
    uint32_t a;
    asm("{ .reg .u64 t; cvta.to.shared.u64 t, %1; cvt.u32.u64 %0, t; }" : "=r"(a) : "l"(p));
    return a;
}

#define CP_ASYNC_16(dst, src) \
    asm volatile("cp.async.cg.shared.global [%0], [%1], 16;" :: "r"(dst), "l"(src))
#define CP_ASYNC_COMMIT() \
    asm volatile("cp.async.commit_group;" ::: "memory")
#define CP_ASYNC_WAIT(n) \
    asm volatile("cp.async.wait_group %0;" :: "n"(n) : "memory")

#define LDSM_X4(r0, r1, r2, r3, addr) \
    asm volatile("ldmatrix.sync.aligned.m8n8.x4.shared.b16 {%0,%1,%2,%3}, [%4];" \
        : "=r"(r0), "=r"(r1), "=r"(r2), "=r"(r3) : "r"(addr))

#define MMA_BF16(d, a, b) \
    asm volatile("mma.sync.aligned.m16n8k16.row.col.f32.bf16.bf16.f32 " \
        "{%0,%1,%2,%3}, {%4,%5,%6,%7}, {%8,%9}, {%0,%1,%2,%3};" \
        : "+f"((d)[0]), "+f"((d)[1]), "+f"((d)[2]), "+f"((d)[3]) \
        : "r"((a)[0]), "r"((a)[1]), "r"((a)[2]), "r"((a)[3]), \
          "r"((b)[0]), "r"((b)[1]))

#define MMA_AB(d, a, b0v, b1v) \
    asm volatile("mma.sync.aligned.m16n8k16.row.col.f32.bf16.bf16.f32 " \
        "{%0,%1,%2,%3}, {%4,%5,%6,%7}, {%8,%9}, {%0,%1,%2,%3};" \
        : "+f"((d)[0]), "+f"((d)[1]), "+f"((d)[2]), "+f"((d)[3]) \
        : "r"((a)[0]), "r"((a)[1]), "r"((a)[2]), "r"((a)[3]), \
          "r"(b0v), "r"(b1v))

__device__ __forceinline__ void split2(float a, float b, uint32_t& hi, uint32_t& lo) {
    __nv_bfloat16 ha = __float2bfloat16(a), hb = __float2bfloat16(b);
    __nv_bfloat162 hh = __halves2bfloat162(ha, hb);
    __nv_bfloat162 ll = __halves2bfloat162(
        __float2bfloat16(a - __bfloat162float(ha)),
        __float2bfloat16(b - __bfloat162float(hb)));
    hi = *(uint32_t*)&hh;
    lo = *(uint32_t*)&ll;
}

// ---------------------------------------------------------------------------
// bf16-split GEMM via mma.sync (now 2 CTAs/SM via launch bounds)
// ---------------------------------------------------------------------------
#define BKc 32
#define ROWB 80
#define TILE_SB (128 * ROWB)
#define STAGE_SB (4 * TILE_SB)
#define MMA_GEMM_SMEM (2 * STAGE_SB)

__global__ __launch_bounds__(256, 2) void gemm_mma_kernel(
    const __nv_bfloat16* __restrict__ Ah, const __nv_bfloat16* __restrict__ Al,
    const __nv_bfloat16* __restrict__ Bh, const __nv_bfloat16* __restrict__ Bl,
    float* __restrict__ C, int N, int K)
{
    extern __shared__ __align__(128) char smem[];
    const uint32_t sb = smem_to_u32(smem);
    const int tid  = threadIdx.x;
    const int lane = tid & 31;
    const int wid  = tid >> 5;
    const int wm   = wid & 1;
    const int wn   = wid >> 1;
    const int m0 = blockIdx.y * 128;
    const int n0 = blockIdx.x * 128;
    const int nchunk = K / BKc;

    float acc[4][4][4];
    #pragma unroll
    for (int i = 0; i < 4; i++)
        #pragma unroll
        for (int j = 0; j < 4; j++)
            #pragma unroll
            for (int r = 0; r < 4; r++) acc[i][j][r] = 0.f;

    const __nv_bfloat16* srcs[4] = {Ah, Al, Bh, Bl};

    auto load_chunk = [&](int c, int buf) {
        #pragma unroll
        for (int t = 0; t < 4; t++) {
            const __nv_bfloat16* src = srcs[t];
            const int rbase = (t < 2) ? m0 : n0;
            #pragma unroll
            for (int i = 0; i < 2; i++) {
                int idx = tid + i * 256;
                int r = idx >> 2;
                int q = idx & 3;
                uint32_t dst = sb + buf * STAGE_SB + t * TILE_SB + r * ROWB + q * 16;
                const void* g = src + (size_t)(rbase + r) * K + c * BKc + q * 8;
                CP_ASYNC_16(dst, g);
            }
        }
        CP_ASYNC_COMMIT();
    };

    load_chunk(0, 0);

    for (int c = 0; c < nchunk; c++) {
        const int buf = c & 1;
        if (c + 1 < nchunk) {
            load_chunk(c + 1, buf ^ 1);
            CP_ASYNC_WAIT(1);
        } else {
            CP_ASYNC_WAIT(0);
        }
        __syncthreads();

        const uint32_t a_base = sb + buf * STAGE_SB;
        const uint32_t b_base = a_base + 2 * TILE_SB;

        #pragma unroll
        for (int ks = 0; ks < 2; ks++) {
            uint32_t ah[4][4], al[4][4];
            #pragma unroll
            for (int mf = 0; mf < 4; mf++) {
                int row = wm * 64 + mf * 16 + (lane & 15);
                uint32_t col = ks * 32 + ((lane >> 4) * 16);
                uint32_t addr = a_base + row * ROWB + col;
                LDSM_X4(ah[mf][0], ah[mf][1], ah[mf][2], ah[mf][3], addr);
                LDSM_X4(al[mf][0], al[mf][1], al[mf][2], al[mf][3], addr + TILE_SB);
            }
            uint32_t bh[4][2], bl[4][2];
            #pragma unroll
            for (int p = 0; p < 2; p++) {
                int row = wn * 32 + p * 16 + ((lane >> 4) << 3) + (lane & 7);
                uint32_t col = ks * 32 + (((lane >> 3) & 1) * 16);
                uint32_t addr = b_base + row * ROWB + col;
                LDSM_X4(bh[2*p][0], bh[2*p][1], bh[2*p+1][0], bh[2*p+1][1], addr);
                LDSM_X4(bl[2*p][0], bl[2*p][1], bl[2*p+1][0], bl[2*p+1][1], addr + TILE_SB);
            }
            #pragma unroll
            for (int mf = 0; mf < 4; mf++)
                #pragma unroll
                for (int nf = 0; nf < 4; nf++)
                    MMA_BF16(acc[mf][nf], ah[mf], bh[nf]);
            #pragma unroll
            for (int mf = 0; mf < 4; mf++)
                #pragma unroll
                for (int nf = 0; nf < 4; nf++)
                    MMA_BF16(acc[mf][nf], ah[mf], bl[nf]);
            #pragma unroll
            for (int mf = 0; mf < 4; mf++)
                #pragma unroll
                for (int nf = 0; nf < 4; nf++)
                    MMA_BF16(acc[mf][nf], al[mf], bh[nf]);
        }
        __syncthreads();
    }

    #pragma unroll
    for (int mf = 0; mf < 4; mf++) {
        #pragma unroll
        for (int nf = 0; nf < 4; nf++) {
            int row = m0 + wm * 64 + mf * 16 + (lane >> 2);
            int col = n0 + wn * 32 + nf * 8 + (lane & 3) * 2;
            *(float2*)&C[(size_t)row * N + col] =
                make_float2(acc[mf][nf][0], acc[mf][nf][1]);
            *(float2*)&C[(size_t)(row + 8) * N + col] =
                make_float2(acc[mf][nf][2], acc[mf][nf][3]);
        }
    }
}

// ---------------------------------------------------------------------------
// Pre-convert qkv fp32 -> attention bf16 hi/lo layouts.
// Grid (T/64, H, B), 256 threads. Q scaled by 0.125 (exact).
// Q,K: [B][H][T][64] token-major. V: [B][H][64][T] transposed (smem tile).
// ---------------------------------------------------------------------------
__global__ __launch_bounds__(256) void preconvert_kernel(
    const float* __restrict__ qkv)
{
    __shared__ float vt[64][65];
    const int tid = threadIdx.x;
    const int t0  = blockIdx.x * 64;
    const int h   = blockIdx.y;
    const int b   = blockIdx.z;
    const size_t bhT = ((size_t)b * Hc + h) * Tc;
    const int bT = b * Tc;

    for (int i = tid; i < 64 * 64; i += 256) {
        int t = i >> 6, c = i & 63;
        size_t base = (size_t)(bT + t0 + t) * QKV_N + h * HDc + c;
        float qv = qkv[base] * 0.125f;
        float kv = qkv[base + Dc];
        float vv = qkv[base + 2 * Dc];
        size_t o = (bhT + t0 + t) * HDc + c;
        __nv_bfloat16 qhh = __float2bfloat16(qv);
        g_qh[o] = qhh;
        g_ql[o] = __float2bfloat16(qv - __bfloat162float(qhh));
        __nv_bfloat16 khh = __float2bfloat16(kv);
        g_kh[o] = khh;
        g_kl[o] = __float2bfloat16(kv - __bfloat162float(khh));
        vt[t][c] = vv;
    }
    __syncthreads();
    for (int i = tid; i < 64 * 64; i += 256) {
        int c = i >> 6, t = i & 63;    // write rows of c, coalesced over t
        float vv = vt[t][c];
        __nv_bfloat16 vhh = __float2bfloat16(vv);
        size_t o = (((size_t)b * Hc + h) * HDc + c) * Tc + t0 + t;
        g_vh[o] = vhh;
        g_vl[o] = __float2bfloat16(vv - __bfloat162float(vhh));
    }
}

// ---------------------------------------------------------------------------
// HMMA flash attention, bf16 operands prefetched via cp.async (double buffer).
// Grid (T/128, H, B), 256 threads (8 warps x 16 rows).
// smem: Q hi/lo 128x144B each; 2 KV stages of {Kh,Kl,Vh,Vl} 64x144B each; pos.
// ---------------------------------------------------------------------------
#define QHB 0
#define QLB 18432
#define STG0 36864
#define STG_SZ 36864          // 4 x 9216
#define KLOFF 9216
#define VHOFF 18432
#define VLOFF 27648
#define POSB (STG0 + 2*STG_SZ)          // 110592
#define ATTN_SMEM (POSB + 2*64*4)       // 111104

__global__ __launch_bounds__(256) void attn_mma_kernel(
    const int* __restrict__ pos,
    __nv_bfloat16* __restrict__ outh,
    __nv_bfloat16* __restrict__ outl)
{
    extern __shared__ __align__(128) char smem[];
    const uint32_t sb = smem_to_u32(smem);
    int* spos = (int*)(smem + POSB);

    const int tid  = threadIdx.x;
    const int lane = tid & 31;
    const int wid  = tid >> 5;

    const int q0  = blockIdx.x * 128;
    const int h   = blockIdx.y;
    const int b   = blockIdx.z;
    const int bt0 = b * Tc + q0;
    const int bT  = b * Tc;
    const size_t bhT = ((size_t)b * Hc + h) * Tc;
    const size_t bhV = ((size_t)b * Hc + h) * HDc;

    // Load Q hi/lo into smem (coalesced 16B)
    for (int i = tid; i < 128 * 8; i += 256) {
        int r = i >> 3, q = i & 7;
        *(uint4*)(smem + QHB + r * 144 + q * 16) =
            *(const uint4*)(g_qh + (bhT + q0 + r) * HDc + q * 8);
        *(uint4*)(smem + QLB + r * 144 + q * 16) =
            *(const uint4*)(g_ql + (bhT + q0 + r) * HDc + q * 8);
    }
    const int pq0 = pos[bt0 + wid * 16 + (lane >> 2)];
    const int pq1 = pos[bt0 + wid * 16 + (lane >> 2) + 8];
    const int pqmax = pos[bt0 + 127];

    // Tile count from sorted positions (cached reads, same for all threads)
    int nt = 1;
    while (nt < Tc / 64 && pos[bT + nt * 64] <= pqmax) nt++;

    __syncthreads();

    uint32_t qh[4][4], ql[4][4];
    #pragma unroll
    for (int ks = 0; ks < 4; ks++) {
        uint32_t addr = sb + QHB + (wid * 16 + (lane & 15)) * 144
                      + ks * 32 + (lane >> 4) * 16;
        LDSM_X4(qh[ks][0], qh[ks][1], qh[ks][2], qh[ks][3], addr);
        LDSM_X4(ql[ks][0], ql[ks][1], ql[ks][2], ql[ks][3], addr + (QLB - QHB));
    }

    auto kv_prefetch = [&](int it, int s) {
        const uint32_t st = sb + STG0 + s * STG_SZ;
        const int k0 = it * 64;
        #pragma unroll
        for (int i = 0; i < 2; i++) {
            int idx = tid + i * 256;       // 0..511
            int j = idx >> 3, q = idx & 7;
            uint32_t d = st + j * 144 + q * 16;
            const __nv_bfloat16* gk = g_kh + (bhT + k0 + j) * HDc + q * 8;
            const __nv_bfloat16* gkl = g_kl + (bhT + k0 + j) * HDc + q * 8;
            const __nv_bfloat16* gv = g_vh + (bhV + j) * Tc + k0 + q * 8;
            const __nv_bfloat16* gvl = g_vl + (bhV + j) * Tc + k0 + q * 8;
            CP_ASYNC_16(d,          gk);
            CP_ASYNC_16(d + KLOFF,  gkl);
            CP_ASYNC_16(d + VHOFF,  gv);
            CP_ASYNC_16(d + VLOFF,  gvl);
        }
        if (tid < 64) spos[s * 64 + tid] = pos[bT + k0 + tid];
        CP_ASYNC_COMMIT();
    };

    float m0 = -1e30f, m1 = -1e30f, l0 = 0.f, l1 = 0.f;
    float oacc[8][4];
    #pragma unroll
    for (int nf = 0; nf < 8; nf++)
        #pragma unroll
        for (int r = 0; r < 4; r++) oacc[nf][r] = 0.f;

    kv_prefetch(0, 0);

    for (int it = 0; it < nt; it++) {
        const int buf = it & 1;
        if (it + 1 < nt) {
            kv_prefetch(it + 1, buf ^ 1);
            CP_ASYNC_WAIT(1);
        } else {
            CP_ASYNC_WAIT(0);
        }
        __syncthreads();

        const uint32_t st = sb + STG0 + buf * STG_SZ;

        // S = Q K^T (hi/lo split, fp32 accum)
        float sacc[8][4];
        #pragma unroll
        for (int nf = 0; nf < 8; nf++)
            #pragma unroll
            for (int r = 0; r < 4; r++) sacc[nf][r] = 0.f;

        #pragma unroll
        for (int ks = 0; ks < 4; ks++) {
            #pragma unroll
            for (int p = 0; p < 4; p++) {
                uint32_t row = p * 16 + ((lane >> 4) << 3) + (lane & 7);
                uint32_t addr = st + row * 144 + ks * 32 + (((lane >> 3) & 1) * 16);
                uint32_t h0, h1, h2, h3, lo0, lo1, lo2, lo3;
                LDSM_X4(h0, h1, h2, h3, addr);
                LDSM_X4(lo0, lo1, lo2, lo3, addr + KLOFF);
                MMA_AB(sacc[2*p],   qh[ks], h0, h1);
                MMA_AB(sacc[2*p],   qh[ks], lo0, lo1);
                MMA_AB(sacc[2*p],   ql[ks], h0, h1);
                MMA_AB(sacc[2*p+1], qh[ks], h2, h3);
                MMA_AB(sacc[2*p+1], qh[ks], lo2, lo3);
                MMA_AB(sacc[2*p+1], ql[ks], h2, h3);
            }
        }

        // Mask + online softmax
        const int* sp = spos + buf * 64;
        float mx0 = -1e30f, mx1 = -1e30f;
        #pragma unroll
        for (int nf = 0; nf < 8; nf++) {
            int jc = nf * 8 + (lane & 3) * 2;
            int p0 = sp[jc], p1 = sp[jc + 1];
            if (p0 > pq0) sacc[nf][0] = -1e30f;
            if (p1 > pq0) sacc[nf][1] = -1e30f;
            if (p0 > pq1) sacc[nf][2] = -1e30f;
            if (p1 > pq1) sacc[nf][3] = -1e30f;
            mx0 = fmaxf(mx0, fmaxf(sacc[nf][0], sacc[nf][1]));
            mx1 = fmaxf(mx1, fmaxf(sacc[nf][2], sacc[nf][3]));
        }
        mx0 = fmaxf(mx0, __shfl_xor_sync(0xffffffffu, mx0, 1));
        mx0 = fmaxf(mx0, __shfl_xor_sync(0xffffffffu, mx0, 2));
        mx1 = fmaxf(mx1, __shfl_xor_sync(0xffffffffu, mx1, 1));
        mx1 = fmaxf(mx1, __shfl_xor_sync(0xffffffffu, mx1, 2));

        float mn0 = fmaxf(m0, mx0), mn1 = fmaxf(m1, mx1);
        float al0 = __expf(m0 - mn0), al1 = __expf(m1 - mn1);
        float ps0 = 0.f, ps1 = 0.f;
        #pragma unroll
        for (int nf = 0; nf < 8; nf++) {
            sacc[nf][0] = __expf(sacc[nf][0] - mn0); ps0 += sacc[nf][0];
            sacc[nf][1] = __expf(sacc[nf][1] - mn0); ps0 += sacc[nf][1];
            sacc[nf][2] = __expf(sacc[nf][2] - mn1); ps1 += sacc[nf][2];
            sacc[nf][3] = __expf(sacc[nf][3] - mn1); ps1 += sacc[nf][3];
        }
        ps0 += __shfl_xor_sync(0xffffffffu, ps0, 1);
        ps0 += __shfl_xor_sync(0xffffffffu, ps0, 2);
        ps1 += __shfl_xor_sync(0xffffffffu, ps1, 1);
        ps1 += __shfl_xor_sync(0xffffffffu, ps1, 2);
        l0 = l0 * al0 + ps0;  m0 = mn0;
        l1 = l1 * al1 + ps1;  m1 = mn1;
        #pragma unroll
        for (int nf = 0; nf < 8; nf++) {
            oacc[nf][0] *= al0; oacc[nf][1] *= al0;
            oacc[nf][2] *= al1; oacc[nf][3] *= al1;
        }

        // O += P V
        #pragma unroll
        for (int ksp = 0; ksp < 4; ksp++) {
            uint32_t ph[4], pl[4];
            split2(sacc[2*ksp][0],   sacc[2*ksp][1],   ph[0], pl[0]);
            split2(sacc[2*ksp][2],   sacc[2*ksp][3],   ph[1], pl[1]);
            split2(sacc[2*ksp+1][0], sacc[2*ksp+1][1], ph[2], pl[2]);
            split2(sacc[2*ksp+1][2], sacc[2*ksp+1][3], ph[3], pl[3]);
            #pragma unroll
            for (int p = 0; p < 4; p++) {
                uint32_t row = p * 16 + ((lane >> 4) << 3) + (lane & 7);
                uint32_t addr = st + VHOFF + row * 144
                              + ksp * 32 + (((lane >> 3) & 1) * 16);
                uint32_t v0, v1, v2, v3, w0, w1, w2, w3;
                LDSM_X4(v0, v1, v2, v3, addr);
                LDSM_X4(w0, w1, w2, w3, addr + (VLOFF - VHOFF));
                MMA_AB(oacc[2*p],   ph, v0, v1);
                MMA_AB(oacc[2*p],   ph, w0, w1);
                MMA_AB(oacc[2*p],   pl, v0, v1);
                MMA_AB(oacc[2*p+1], ph, v2, v3);
                MMA_AB(oacc[2*p+1], ph, w2, w3);
                MMA_AB(oacc[2*p+1], pl, v2, v3);
            }
        }
        __syncthreads();
    }

    // Epilogue: normalize + fused bf16 hi/lo split for the out-projection
    const float inv0 = 1.0f / l0;
    const float inv1 = 1.0f / l1;
    const int r0 = bt0 + wid * 16 + (lane >> 2);
    const int r1 = r0 + 8;
    #pragma unroll
    for (int nf = 0; nf < 8; nf++) {
        int col = h * HDc + nf * 8 + (lane & 3) * 2;
        uint32_t hi, lo;
        split2(oacc[nf][0] * inv0, oacc[nf][1] * inv0, hi, lo);
        *(uint32_t*)&outh[(size_t)r0 * Dc + col] = hi;
        *(uint32_t*)&outl[(size_t)r0 * Dc + col] = lo;
        split2(oacc[nf][2] * inv1, oacc[nf][3] * inv1, hi, lo);
        *(uint32_t*)&outh[(size_t)r1 * Dc + col] = hi;
        *(uint32_t*)&outl[(size_t)r1 * Dc + col] = lo;
    }
}

// ---------------------------------------------------------------------------
// fp32 -> bf16 hi/lo split (vectorized x4)
// ---------------------------------------------------------------------------
__global__ __launch_bounds__(256) void split_kernel(
    const float4* __restrict__ in, __nv_bfloat162* __restrict__ hi,
    __nv_bfloat162* __restrict__ lo, int n4)
{
    int i = blockIdx.x * blockDim.x + threadIdx.x;
    if (i >= n4) return;
    float4 v = in[i];
    __nv_bfloat16 h0 = __float2bfloat16(v.x);
    __nv_bfloat16 h1 = __float2bfloat16(v.y);
    __nv_bfloat16 h2 = __float2bfloat16(v.z);
    __nv_bfloat16 h3 = __float2bfloat16(v.w);
    hi[2*i]   = __halves2bfloat162(h0, h1);
    hi[2*i+1] = __halves2bfloat162(h2, h3);
    lo[2*i]   = __halves2bfloat162(__float2bfloat16(v.x - __bfloat162float(h0)),
                                   __float2bfloat16(v.y - __bfloat162float(h1)));
    lo[2*i+1] = __halves2bfloat162(__float2bfloat16(v.z - __bfloat162float(h2)),
                                   __float2bfloat16(v.w - __bfloat162float(h3)));
}

// ---------------------------------------------------------------------------
// W [K,N] fp32 -> W^T [N,K] bf16 hi/lo (32x32 smem tiles)
// ---------------------------------------------------------------------------
__global__ __launch_bounds__(256) void transpose_split_kernel(
    const float* __restrict__ in, __nv_bfloat16* __restrict__ hiT,
    __nv_bfloat16* __restrict__ loT, int K, int N)
{
    __shared__ float t[32][33];
    const int tx = threadIdx.x;
    const int ty = threadIdx.y;
    const int n0 = blockIdx.x * 32;
    const int k0 = blockIdx.y * 32;
    #pragma unroll
    for (int i = 0; i < 4; i++) {
        int row = ty + i * 8;
        t[row][tx] = in[(size_t)(k0 + row) * N + n0 + tx];
    }
    __syncthreads();
    #pragma unroll
    for (int i = 0; i < 4; i++) {
        int row = ty + i * 8;
        float v = t[tx][row];
        __nv_bfloat16 h = __float2bfloat16(v);
        size_t o = (size_t)(n0 + row) * K + k0 + tx;
        hiT[o] = h;
        loT[o] = __float2bfloat16(v - __bfloat162float(h));
    }
}

// ---------------------------------------------------------------------------
extern "C" void kernel_launch(void* const* d_in, const int* in_sizes, int n_in,
                              void* d_out, int out_size)
{
    const float* x    = (const float*)d_in[0];
    const int*   pos  = (const int*)  d_in[1];
    const float* Wqkv = (const float*)d_in[2];
    const float* Wout = (const float*)d_in[3];
    float* out = (float*)d_out;

    float *qkv_ptr = nullptr;
    __nv_bfloat16 *xh, *xl, *wqh, *wql, *woh, *wol, *ah, *al;
    cudaGetSymbolAddress((void**)&qkv_ptr,  g_qkv);
    cudaGetSymbolAddress((void**)&xh,  g_xh);
    cudaGetSymbolAddress((void**)&xl,  g_xl);
    cudaGetSymbolAddress((void**)&wqh, g_wqkv_h);
    cudaGetSymbolAddress((void**)&wql, g_wqkv_l);
    cudaGetSymbolAddress((void**)&woh, g_wout_h);
    cudaGetSymbolAddress((void**)&wol, g_wout_l);
    cudaGetSymbolAddress((void**)&ah,  g_ah);
    cudaGetSymbolAddress((void**)&al,  g_al);

    static bool attr_set = false;
    if (!attr_set) {
        cudaFuncSetAttribute(gemm_mma_kernel,
                             cudaFuncAttributeMaxDynamicSharedMemorySize, MMA_GEMM_SMEM);
        cudaFuncSetAttribute(attn_mma_kernel,
                             cudaFuncAttributeMaxDynamicSharedMemorySize, ATTN_SMEM);
        attr_set = true;
    }

    // 0) Input splits
    {
        int n4 = BT * Dc / 4;
        split_kernel<<<(n4 + 255) / 256, 256>>>(
            (const float4*)x, (__nv_bfloat162*)xh, (__nv_bfloat162*)xl, n4);
    }
    {
        dim3 grid(QKV_N / 32, Dc / 32);
        transpose_split_kernel<<<grid, dim3(32, 8)>>>(Wqkv, wqh, wql, Dc, QKV_N);
    }
    {
        dim3 grid(Dc / 32, Dc / 32);
        transpose_split_kernel<<<grid, dim3(32, 8)>>>(Wout, woh, wol, Dc, Dc);
    }

    // 1) QKV projection on HMMA
    {
        dim3 grid(QKV_N / 128, BT / 128);
        gemm_mma_kernel<<<grid, 256, MMA_GEMM_SMEM>>>(
            xh, xl, wqh, wql, qkv_ptr, QKV_N, Dc);
    }

    // 2) Pre-convert Q/K/V to bf16 hi/lo attention layouts (V transposed)
    {
        dim3 grid(Tc / 64, Hc, Bc);
        preconvert_kernel<<<grid, 256>>>(qkv_ptr);
    }

    // 3) Attention on HMMA (cp.async bf16 operands, fused output split)
    {
        dim3 grid(Tc / 128, Hc, Bc);
        attn_mma_kernel<<<grid, 256, ATTN_SMEM>>>(pos, ah, al);
    }

    // 4) Out projection on HMMA
    {
        dim3 grid(Dc / 128, BT / 128);
        gemm_mma_kernel<<<grid, 256, MMA_GEMM_SMEM>>>(
            ah, al, woh, wol, out, Dc, Dc);
    }
}